// round 4
// baseline (speedup 1.0000x reference)
#include <cuda_runtime.h>
#include <cuda_bf16.h>

// 2D Haar DWT, single level.
// Input  x  : (B=16, C=64, H=256, W=256) fp32
// Output out: (B, C*4, H/2=128, W/2=128) fp32, planes ordered [cA, cH, cV, cD]
//
// Each thread processes one (bc, h) row position and EIGHT output columns:
//   loads 4x float4 from input rows 2h and 2h+1 (8 independent streaming loads),
//   writes 2x float4 to each of the 4 output planes (streaming 16B stores).

#define B_  16
#define C_  64
#define H_  256
#define W_  256
#define H2  (H_/2)          // 128
#define W2  (W_/2)          // 128
#define OCTS (W2/8)         // 16 groups of 8 output cols per output row
#define PLANE (H2*W2)       // 16384 elements per output plane

__device__ __forceinline__ void haar4(const float4 t, const float4 u,
                                      float4& A, float4& Hc, float4& V, float4& D)
{
    // t = a0 b0 a1 b1 (top row), u = c0 d0 c1 d1 (bottom row)
    {
        float a = t.x, b = t.y, c = u.x, d = u.y;
        A.x = (a + b + c + d) * 0.5f;  Hc.x = (c + d - a - b) * 0.5f;
        V.x = (b + d - a - c) * 0.5f;  D.x  = (a - b - c + d) * 0.5f;
    }
    {
        float a = t.z, b = t.w, c = u.z, d = u.w;
        A.y = (a + b + c + d) * 0.5f;  Hc.y = (c + d - a - b) * 0.5f;
        V.y = (b + d - a - c) * 0.5f;  D.y  = (a - b - c + d) * 0.5f;
    }
}

__global__ __launch_bounds__(256) void dwt_haar_kernel(
    const float* __restrict__ x, float* __restrict__ out)
{
    int idx = blockIdx.x * blockDim.x + threadIdx.x;
    // idx in [0, B*C*H2*OCTS) = 16*64*128*16 = 2,097,152
    int wo = idx & (OCTS - 1);             // which group of 8 output cols
    int h  = (idx >> 4) & (H2 - 1);        // output row
    int bc = idx >> 11;                    // 0 .. B*C-1 = 1023

    const float4* row0 = reinterpret_cast<const float4*>(
        x + (bc * H_ + 2 * h) * W_ + wo * 16);
    const float4* row1 = reinterpret_cast<const float4*>(
        x + (bc * H_ + 2 * h + 1) * W_ + wo * 16);

    // 8 independent streaming loads up front (MLP=8)
    float4 t0 = __ldcs(row0);
    float4 t1 = __ldcs(row0 + 1);
    float4 t2 = __ldcs(row0 + 2);
    float4 t3 = __ldcs(row0 + 3);
    float4 u0 = __ldcs(row1);
    float4 u1 = __ldcs(row1 + 1);
    float4 u2 = __ldcs(row1 + 2);
    float4 u3 = __ldcs(row1 + 3);

    float4 A0, H0, V0, D0, A1, H1, V1, D1;
    // first float4 of outputs <- t0,t1 / u0,u1
    {
        float4 lo, hi;
        haar4(t0, u0, lo, hi, V0, D0);   // temp misuse avoided below; do explicitly
    }
    // Explicit, simple form:
    {
        float2 a2;
        (void)a2;
    }
    // compute pairwise: outputs 0..3 come from (t0,u0) and (t1,u1)
    {
        float4 pA, pH, pV, pD;
        haar4(t0, u0, pA, pH, pV, pD);
        A0.x = pA.x; A0.y = pA.y; H0.x = pH.x; H0.y = pH.y;
        V0.x = pV.x; V0.y = pV.y; D0.x = pD.x; D0.y = pD.y;
        haar4(t1, u1, pA, pH, pV, pD);
        A0.z = pA.x; A0.w = pA.y; H0.z = pH.x; H0.w = pH.y;
        V0.z = pV.x; V0.w = pV.y; D0.z = pD.x; D0.w = pD.y;
        haar4(t2, u2, pA, pH, pV, pD);
        A1.x = pA.x; A1.y = pA.y; H1.x = pH.x; H1.y = pH.y;
        V1.x = pV.x; V1.y = pV.y; D1.x = pD.x; D1.y = pD.y;
        haar4(t3, u3, pA, pH, pV, pD);
        A1.z = pA.x; A1.w = pA.y; H1.z = pH.x; H1.w = pH.y;
        V1.z = pV.x; V1.w = pV.y; D1.z = pD.x; D1.w = pD.y;
    }

    // output channel = bc*4 + k ; out[(bc*4 + k)*PLANE + h*W2 + 8*wo]
    float4* obase = reinterpret_cast<float4*>(
        out + (bc * 4) * PLANE + h * W2 + 8 * wo);
    const int pstride = PLANE / 4;   // float4 stride between planes
    __stcs(obase,                   A0);
    __stcs(obase + 1,               A1);
    __stcs(obase + pstride,         H0);
    __stcs(obase + pstride + 1,     H1);
    __stcs(obase + 2 * pstride,     V0);
    __stcs(obase + 2 * pstride + 1, V1);
    __stcs(obase + 3 * pstride,     D0);
    __stcs(obase + 3 * pstride + 1, D1);
}

extern "C" void kernel_launch(void* const* d_in, const int* in_sizes, int n_in,
                              void* d_out, int out_size) {
    const float* x = (const float*)d_in[0];
    float* out = (float*)d_out;
    int total_threads = B_ * C_ * H2 * OCTS;    // 2,097,152
    int block = 256;
    int grid = total_threads / block;           // 8192
    dwt_haar_kernel<<<grid, block>>>(x, out);
}

// round 5
// speedup vs baseline: 1.1417x; 1.1417x over previous
#include <cuda_runtime.h>
#include <cuda_bf16.h>

// 2D Haar DWT, single level.
// Input  x  : (B=16, C=64, H=256, W=256) fp32
// Output out: (B, C*4, H/2=128, W/2=128) fp32, planes ordered [cA, cH, cV, cD]
//
// One WARP per (bc, h) input row-pair. Thread `lane` loads float4s at
// row0[lane], row0[lane+32], row1[lane], row1[lane+32] -- every LDG.128 is a
// dense 512B warp transaction (MLP=4, perfectly coalesced). Each float4 pair
// (top,bottom) yields a float2 of each Haar coefficient; stores are dense
// 256B STG.64 warp transactions into each of the 4 output planes.

#define B_  16
#define C_  64
#define H_  256
#define W_  256
#define H2  (H_/2)          // 128
#define W2  (W_/2)          // 128
#define PLANE (H2*W2)       // 16384 elements per output plane

__device__ __forceinline__ void haar2(const float4 t, const float4 u,
                                      float2& A, float2& Hc, float2& V, float2& D)
{
    // t = a0 b0 a1 b1 (top row), u = c0 d0 c1 d1 (bottom row)
    {
        float a = t.x, b = t.y, c = u.x, d = u.y;
        A.x = (a + b + c + d) * 0.5f;  Hc.x = (c + d - a - b) * 0.5f;
        V.x = (b + d - a - c) * 0.5f;  D.x  = (a - b - c + d) * 0.5f;
    }
    {
        float a = t.z, b = t.w, c = u.z, d = u.w;
        A.y = (a + b + c + d) * 0.5f;  Hc.y = (c + d - a - b) * 0.5f;
        V.y = (b + d - a - c) * 0.5f;  D.y  = (a - b - c + d) * 0.5f;
    }
}

__global__ __launch_bounds__(256) void dwt_haar_kernel(
    const float* __restrict__ x, float* __restrict__ out)
{
    int tid  = blockIdx.x * blockDim.x + threadIdx.x;
    int lane = tid & 31;
    int w    = tid >> 5;                 // warp id in [0, B*C*H2) = 131072
    int h    = w & (H2 - 1);             // output row
    int bc   = w >> 7;                   // 0 .. B*C-1 = 1023

    const float4* row0 = reinterpret_cast<const float4*>(
        x + (bc * H_ + 2 * h) * W_);
    const float4* row1 = reinterpret_cast<const float4*>(
        x + (bc * H_ + 2 * h + 1) * W_);

    // 4 independent, fully-coalesced streaming loads (each = dense 512B/warp)
    float4 t0 = __ldcs(row0 + lane);
    float4 t1 = __ldcs(row0 + lane + 32);
    float4 u0 = __ldcs(row1 + lane);
    float4 u1 = __ldcs(row1 + lane + 32);

    float2 A0, H0, V0, D0, A1, H1, V1, D1;
    haar2(t0, u0, A0, H0, V0, D0);   // output float2 index: lane
    haar2(t1, u1, A1, H1, V1, D1);   // output float2 index: lane + 32

    // out plane base for this (bc, h): channel bc*4 + k
    float2* o2 = reinterpret_cast<float2*>(out + (bc * 4) * PLANE + h * W2);
    const int pstride = PLANE / 2;   // float2 stride between planes (8192)

    __stcs(o2 + lane,                    A0);
    __stcs(o2 + lane + 32,               A1);
    __stcs(o2 + pstride + lane,          H0);
    __stcs(o2 + pstride + lane + 32,     H1);
    __stcs(o2 + 2 * pstride + lane,      V0);
    __stcs(o2 + 2 * pstride + lane + 32, V1);
    __stcs(o2 + 3 * pstride + lane,      D0);
    __stcs(o2 + 3 * pstride + lane + 32, D1);
}

extern "C" void kernel_launch(void* const* d_in, const int* in_sizes, int n_in,
                              void* d_out, int out_size) {
    const float* x = (const float*)d_in[0];
    float* out = (float*)d_out;
    int total_warps  = B_ * C_ * H2;            // 131072
    int block = 256;                            // 8 warps
    int grid = total_warps * 32 / block;        // 16384
    dwt_haar_kernel<<<grid, block>>>(x, out);
}